// round 10
// baseline (speedup 1.0000x reference)
#include <cuda_runtime.h>
#include <math.h>
#include <stdint.h>

// Problem shape (fixed)
#define NTOK 8192      // B*T
#define DIM  512       // D
#define FDIM 1024      // F
#define NEXP 8         // E

// ---------------- scratch ----------------
__device__ int   g_expert_count[NEXP];
__device__ int   g_expert_pair[NEXP * NTOK];
__device__ float g_pair_w[NTOK * 2];
__device__ float g_hbuf[(size_t)NTOK * 2 * FDIM];        // SwiGLU act (tf32-rounded)
__device__ float g_x_tf[(size_t)NTOK * DIM];             // tf32-rounded x
__device__ float g_wgut[(size_t)NEXP * 2 * FDIM * DIM];  // [e][n(2F)][k(D)] transposed+rounded
__device__ float g_wdt[(size_t)NEXP * DIM * FDIM];       // [e][n(D)][k(F)] transposed+rounded

// ---------------- PTX helpers ----------------
__device__ __forceinline__ uint32_t smem_u32(const void* p) {
    return (uint32_t)__cvta_generic_to_shared(p);
}
__device__ __forceinline__ void cpa16(uint32_t dst, const void* src, int sz) {
    asm volatile("cp.async.cg.shared.global [%0], [%1], 16, %2;\n"
                 :: "r"(dst), "l"(src), "r"(sz));
}
__device__ __forceinline__ void cp_commit() { asm volatile("cp.async.commit_group;\n"); }
template <int N>
__device__ __forceinline__ void cp_wait() { asm volatile("cp.async.wait_group %0;\n" :: "n"(N)); }
__device__ __forceinline__ uint32_t f2tf(float f) {
    uint32_t u; asm("cvt.rna.tf32.f32 %0, %1;" : "=r"(u) : "f"(f)); return u;
}
__device__ __forceinline__ void ldsm4(uint32_t* r, uint32_t addr) {
    asm volatile("ldmatrix.sync.aligned.m8n8.x4.shared.b16 {%0,%1,%2,%3}, [%4];"
                 : "=r"(r[0]), "=r"(r[1]), "=r"(r[2]), "=r"(r[3]) : "r"(addr));
}
__device__ __forceinline__ void mma8(float* d, const uint32_t* a, const uint32_t* b) {
    asm volatile("mma.sync.aligned.m16n8k8.row.col.f32.tf32.tf32.f32 "
                 "{%0,%1,%2,%3}, {%4,%5,%6,%7}, {%8,%9}, {%0,%1,%2,%3};\n"
                 : "+f"(d[0]), "+f"(d[1]), "+f"(d[2]), "+f"(d[3])
                 : "r"(a[0]), "r"(a[1]), "r"(a[2]), "r"(a[3]),
                   "r"(b[0]), "r"(b[1]));
}

// ---------------- kernel: pre-round x -> tf32(rna) ----------------
__global__ void __launch_bounds__(256) round_tf32_kernel(const float* __restrict__ src,
                                                         float* __restrict__ dst, int n4) {
    int i = blockIdx.x * 256 + threadIdx.x;
    if (i >= n4) return;
    float4 v = reinterpret_cast<const float4*>(src)[i];
    float4 o;
    o.x = __uint_as_float(f2tf(v.x));
    o.y = __uint_as_float(f2tf(v.y));
    o.z = __uint_as_float(f2tf(v.z));
    o.w = __uint_as_float(f2tf(v.w));
    reinterpret_cast<float4*>(dst)[i] = o;
}

// ---------------- kernel: fused transpose + tf32(rna) round ----------------
// in [z][R][C] -> out [z][C][R]; CTA does a 128(R) x 32(C) tile as 4 32x32 subtiles (MLP=4)
__global__ void __launch_bounds__(256) transpose_tf32_kernel(const float* __restrict__ in,
                                                             float* __restrict__ out,
                                                             int R, int C) {
    __shared__ float t[4][32][33];
    size_t zoff = (size_t)blockIdx.z * (size_t)R * C;
    in += zoff; out += zoff;
    int r0 = blockIdx.y * 128, c0 = blockIdx.x * 32;
    int tid = threadIdx.x;
    int row32 = tid >> 3, c4 = tid & 7;
    float4 v[4];
#pragma unroll
    for (int i = 0; i < 4; i++)
        v[i] = *reinterpret_cast<const float4*>(
            in + (size_t)(r0 + i * 32 + row32) * C + c0 + c4 * 4);
#pragma unroll
    for (int i = 0; i < 4; i++) {
        t[i][c4 * 4 + 0][row32] = v[i].x;
        t[i][c4 * 4 + 1][row32] = v[i].y;
        t[i][c4 * 4 + 2][row32] = v[i].z;
        t[i][c4 * 4 + 3][row32] = v[i].w;
    }
    __syncthreads();
    int oc = tid >> 3, o4 = tid & 7;
#pragma unroll
    for (int i = 0; i < 4; i++) {
        float4 o;
        o.x = __uint_as_float(f2tf(t[i][oc][o4 * 4 + 0]));
        o.y = __uint_as_float(f2tf(t[i][oc][o4 * 4 + 1]));
        o.z = __uint_as_float(f2tf(t[i][oc][o4 * 4 + 2]));
        o.w = __uint_as_float(f2tf(t[i][oc][o4 * 4 + 3]));
        *reinterpret_cast<float4*>(out + (size_t)(c0 + oc) * R + r0 + i * 32 + o4 * 4) = o;
    }
}

// ---------------- kernel 0: zero counts ----------------
__global__ void zero_counts_kernel() {
    if (threadIdx.x < NEXP) g_expert_count[threadIdx.x] = 0;
}

// ---------------- kernel 1: router + dispatch ----------------
__global__ void router_kernel(const float* __restrict__ x,
                              const float* __restrict__ rw,
                              const float* __restrict__ rb) {
    __shared__ float sw[NEXP * DIM];
    int tid = threadIdx.x;
    for (int i = tid; i < NEXP * DIM; i += 256) sw[i] = rw[i];
    __syncthreads();

    int warp = tid >> 5, lane = tid & 31;
    int token = blockIdx.x * 8 + warp;
    if (token >= NTOK) return;

    const float* xr = x + (size_t)token * DIM;
    float acc[NEXP];
#pragma unroll
    for (int e = 0; e < NEXP; e++) acc[e] = 0.f;
    for (int i = lane; i < DIM; i += 32) {
        float xv = xr[i];
#pragma unroll
        for (int e = 0; e < NEXP; e++) acc[e] += xv * sw[e * DIM + i];
    }
#pragma unroll
    for (int e = 0; e < NEXP; e++) {
#pragma unroll
        for (int o = 16; o > 0; o >>= 1)
            acc[e] += __shfl_xor_sync(0xffffffffu, acc[e], o);
    }
    if (lane == 0) {
        float l[NEXP];
#pragma unroll
        for (int e = 0; e < NEXP; e++) l[e] = acc[e] + rb[e];
        int e1 = 0; float b1 = l[0];
#pragma unroll
        for (int e = 1; e < NEXP; e++) if (l[e] > b1) { b1 = l[e]; e1 = e; }
        int e2 = -1; float b2 = -INFINITY;
#pragma unroll
        for (int e = 0; e < NEXP; e++)
            if (e != e1 && l[e] > b2) { b2 = l[e]; e2 = e; }
        float t  = expf(b2 - b1);
        float w1 = 1.f / (1.f + t);
        float w2 = t   / (1.f + t);
        int pos1 = atomicAdd(&g_expert_count[e1], 1);
        g_expert_pair[e1 * NTOK + pos1] = token * 2;
        g_pair_w[token * 2] = w1;
        int pos2 = atomicAdd(&g_expert_count[e2], 1);
        g_expert_pair[e2 * NTOK + pos2] = token * 2 + 1;
        g_pair_w[token * 2 + 1] = w2;
    }
}

// ---------------- tensor-GEMM config ----------------
#define BM 128
#define BN 64
#define BK 32
#define BKP 36            // smem row stride (words) for both A (m-rows) and B (n-rows)
#define ASZ (BM * BKP)    // 4608 words
#define BSZ (BN * BKP)    // 2304 words (64 n-rows x 36)
// 8 warps = 4 m-groups x 2 n-groups; warp tile 32x32

// ---------------- kernel 2: gate_up GEMM + SwiGLU ----------------
// grid = (FDIM/BN, NTOK/BM, NEXP); B from transposed weights [n][k]
__global__ void __launch_bounds__(256)
gateup_kernel(const float* __restrict__ x, const float* __restrict__ wgut) {
    int e = blockIdx.z;
    int count = g_expert_count[e];
    int m0 = blockIdx.y * BM;
    if (m0 >= count) return;
    int n0 = blockIdx.x * BN;
    int tid = threadIdx.x;

    extern __shared__ float dynsmem[];
    __shared__ int s_pr[BM];
    if (tid < BM) {
        int m = m0 + tid;
        s_pr[tid] = (m < count) ? g_expert_pair[e * NTOK + m] : -1;
    }
    __syncthreads();

    const float* wge = wgut + (size_t)e * (2 * FDIM) * DIM;
    float* stage0 = dynsmem;
    float* stage1 = dynsmem + (ASZ + 2 * BSZ);

    // A loader: 4 x 16B chunks (k-contiguous rows of gathered tokens)
    int am[4], ac[4], asz[4];
    const float* asrc[4];
#pragma unroll
    for (int j = 0; j < 4; j++) {
        int idx = tid + 256 * j;
        am[j] = idx >> 3; ac[j] = (idx & 7) * 4;
        int pr = s_pr[am[j]];
        asz[j]  = (pr >= 0) ? 16 : 0;
        asrc[j] = (pr >= 0) ? (x + (size_t)(pr >> 1) * DIM + ac[j]) : x;
    }
    // B loader: 2 x 16B chunks per matrix; rows are n, k-contiguous
    int brow[2], bch[2];
#pragma unroll
    for (int j = 0; j < 2; j++) {
        int idx = tid + 256 * j;
        brow[j] = idx >> 3; bch[j] = (idx & 7) * 4;
    }

    auto load_tile = [&](int kt, float* st) {
        float* As = st; float* Bg = st + ASZ; float* Bu = Bg + BSZ;
        int k0 = kt * BK;
#pragma unroll
        for (int j = 0; j < 4; j++)
            cpa16(smem_u32(As + am[j] * BKP + ac[j]), asrc[j] + k0, asz[j]);
#pragma unroll
        for (int j = 0; j < 2; j++) {
            cpa16(smem_u32(Bg + brow[j] * BKP + bch[j]),
                  wge + (size_t)(n0 + brow[j]) * DIM + k0 + bch[j], 16);
            cpa16(smem_u32(Bu + brow[j] * BKP + bch[j]),
                  wge + (size_t)(FDIM + n0 + brow[j]) * DIM + k0 + bch[j], 16);
        }
    };

    int lane = tid & 31, warp = tid >> 5;
    int wm = (warp & 3) * 32, wn = (warp >> 2) * 32;
    int r = lane >> 2, c = lane & 3;
    int lrow = lane & 15, lcol = (lane >> 4) * 4;       // A ldmatrix lane map
    int nbr  = ((lane >> 4) * 8) + (lane & 7);          // B ldmatrix: n row within 16-block
    int kh   = ((lane >> 3) & 1) * 4;                   // B ldmatrix: k half

    float accg[2][4][4] = {{{0.f}}};
    float accu[2][4][4] = {{{0.f}}};

    load_tile(0, stage0);
    cp_commit();
    const int KT = DIM / BK;   // 16
    for (int kt = 0; kt < KT; kt++) {
        if (kt + 1 < KT) load_tile(kt + 1, ((kt + 1) & 1) ? stage1 : stage0);
        cp_commit();
        cp_wait<1>();
        __syncthreads();
        const float* As = (kt & 1) ? stage1 : stage0;
        const float* Bg = As + ASZ;
        const float* Bu = Bg + BSZ;
        uint32_t abase = smem_u32(As + (wm + lrow) * BKP + lcol);
        uint32_t gbase = smem_u32(Bg + (wn + nbr) * BKP + kh);
        uint32_t ubase = smem_u32(Bu + (wn + nbr) * BKP + kh);
#pragma unroll
        for (int k8 = 0; k8 < BK / 8; k8++) {
            uint32_t a[2][4];
#pragma unroll
            for (int i = 0; i < 2; i++)
                ldsm4(a[i], abase + i * (16 * BKP * 4) + k8 * 32);
            uint32_t bg4[2][4], bu4[2][4];
#pragma unroll
            for (int jj = 0; jj < 2; jj++) {
                ldsm4(bg4[jj], gbase + jj * (16 * BKP * 4) + k8 * 32);
                ldsm4(bu4[jj], ubase + jj * (16 * BKP * 4) + k8 * 32);
            }
#pragma unroll
            for (int i = 0; i < 2; i++)
#pragma unroll
                for (int j = 0; j < 4; j++) {
                    mma8(accg[i][j], a[i], &bg4[j >> 1][(j & 1) * 2]);
                    mma8(accu[i][j], a[i], &bu4[j >> 1][(j & 1) * 2]);
                }
        }
        __syncthreads();
    }

    // epilogue: silu(g)*u -> hbuf (tf32-rounded so down needs no A cvt)
#pragma unroll
    for (int i = 0; i < 2; i++) {
#pragma unroll
        for (int rr = 0; rr < 2; rr++) {
            int mrow = wm + i * 16 + r + rr * 8;
            int pr = s_pr[mrow];
            if (pr < 0) continue;
            float* hp = g_hbuf + (size_t)pr * FDIM + n0 + wn;
#pragma unroll
            for (int j = 0; j < 4; j++) {
                float g0 = accg[i][j][rr * 2 + 0], g1 = accg[i][j][rr * 2 + 1];
                float u0 = accu[i][j][rr * 2 + 0], u1 = accu[i][j][rr * 2 + 1];
                float h0 = g0 / (1.f + expf(-g0)) * u0;
                float h1 = g1 / (1.f + expf(-g1)) * u1;
                float2 hv = make_float2(__uint_as_float(f2tf(h0)),
                                        __uint_as_float(f2tf(h1)));
                *reinterpret_cast<float2*>(hp + j * 8 + 2 * c) = hv;
            }
        }
    }
}

// ---------------- kernel 3: down GEMM + weighted combine ----------------
// grid = (DIM/BN, NTOK/BM, NEXP); B from transposed wd [n][k]
__global__ void __launch_bounds__(256)
down_kernel(const float* __restrict__ wdt, float* __restrict__ out) {
    int e = blockIdx.z;
    int count = g_expert_count[e];
    int m0 = blockIdx.y * BM;
    if (m0 >= count) return;
    int n0 = blockIdx.x * BN;
    int tid = threadIdx.x;

    extern __shared__ float dynsmem[];
    __shared__ int   s_pr[BM];
    __shared__ float s_w[BM];
    if (tid < BM) {
        int m = m0 + tid;
        int pr = (m < count) ? g_expert_pair[e * NTOK + m] : -1;
        s_pr[tid] = pr;
        s_w[tid]  = (pr >= 0) ? g_pair_w[pr] : 0.f;
    }
    __syncthreads();

    const float* wde = wdt + (size_t)e * DIM * FDIM;
    float* stage0 = dynsmem;
    float* stage1 = dynsmem + (ASZ + BSZ);

    int am[4], ac[4], asz[4];
    const float* asrc[4];
#pragma unroll
    for (int j = 0; j < 4; j++) {
        int idx = tid + 256 * j;
        am[j] = idx >> 3; ac[j] = (idx & 7) * 4;
        int pr = s_pr[am[j]];
        asz[j]  = (pr >= 0) ? 16 : 0;
        asrc[j] = (pr >= 0) ? (g_hbuf + (size_t)pr * FDIM + ac[j]) : g_hbuf;
    }
    int brow[2], bch[2];
#pragma unroll
    for (int j = 0; j < 2; j++) {
        int idx = tid + 256 * j;
        brow[j] = idx >> 3; bch[j] = (idx & 7) * 4;
    }

    auto load_tile = [&](int kt, float* st) {
        float* As = st; float* Bs = st + ASZ;
        int k0 = kt * BK;
#pragma unroll
        for (int j = 0; j < 4; j++)
            cpa16(smem_u32(As + am[j] * BKP + ac[j]), asrc[j] + k0, asz[j]);
#pragma unroll
        for (int j = 0; j < 2; j++)
            cpa16(smem_u32(Bs + brow[j] * BKP + bch[j]),
                  wde + (size_t)(n0 + brow[j]) * FDIM + k0 + bch[j], 16);
    };

    int lane = tid & 31, warp = tid >> 5;
    int wm = (warp & 3) * 32, wn = (warp >> 2) * 32;
    int r = lane >> 2, c = lane & 3;
    int lrow = lane & 15, lcol = (lane >> 4) * 4;
    int nbr  = ((lane >> 4) * 8) + (lane & 7);
    int kh   = ((lane >> 3) & 1) * 4;

    float acc[2][4][4] = {{{0.f}}};

    load_tile(0, stage0);
    cp_commit();
    const int KT = FDIM / BK;  // 32
    for (int kt = 0; kt < KT; kt++) {
        if (kt + 1 < KT) load_tile(kt + 1, ((kt + 1) & 1) ? stage1 : stage0);
        cp_commit();
        cp_wait<1>();
        __syncthreads();
        const float* As = (kt & 1) ? stage1 : stage0;
        const float* Bs = As + ASZ;
        uint32_t abase = smem_u32(As + (wm + lrow) * BKP + lcol);
        uint32_t bbase = smem_u32(Bs + (wn + nbr) * BKP + kh);
#pragma unroll
        for (int k8 = 0; k8 < BK / 8; k8++) {
            uint32_t a[2][4];
#pragma unroll
            for (int i = 0; i < 2; i++)
                ldsm4(a[i], abase + i * (16 * BKP * 4) + k8 * 32);
            uint32_t b4[2][4];
#pragma unroll
            for (int jj = 0; jj < 2; jj++)
                ldsm4(b4[jj], bbase + jj * (16 * BKP * 4) + k8 * 32);
#pragma unroll
            for (int i = 0; i < 2; i++)
#pragma unroll
                for (int j = 0; j < 4; j++)
                    mma8(acc[i][j], a[i], &b4[j >> 1][(j & 1) * 2]);
        }
        __syncthreads();
    }

    // epilogue: out += w * acc (2 commutative atomics per element)
#pragma unroll
    for (int i = 0; i < 2; i++) {
#pragma unroll
        for (int rr = 0; rr < 2; rr++) {
            int mrow = wm + i * 16 + r + rr * 8;
            int pr = s_pr[mrow];
            if (pr < 0) continue;
            int token = pr >> 1;
            float w = s_w[mrow];
            float* op = out + (size_t)token * DIM + n0 + wn;
#pragma unroll
            for (int j = 0; j < 4; j++) {
                atomicAdd(op + j * 8 + 2 * c,     w * acc[i][j][rr * 2 + 0]);
                atomicAdd(op + j * 8 + 2 * c + 1, w * acc[i][j][rr * 2 + 1]);
            }
        }
    }
}

// ---------------- launch ----------------
extern "C" void kernel_launch(void* const* d_in, const int* in_sizes, int n_in,
                              void* d_out, int out_size) {
    const float* x   = (const float*)d_in[0];
    const float* rw  = (const float*)d_in[1];
    const float* rb  = (const float*)d_in[2];
    const float* wgu = (const float*)d_in[3];
    const float* wd  = (const float*)d_in[4];
    float* out = (float*)d_out;

    const int gu_smem = 2 * (ASZ + 2 * BSZ) * 4;   // 73728 B
    const int dn_smem = 2 * (ASZ + BSZ) * 4;       // 55296 B
    cudaFuncSetAttribute(gateup_kernel, cudaFuncAttributeMaxDynamicSharedMemorySize, gu_smem);
    cudaFuncSetAttribute(down_kernel,   cudaFuncAttributeMaxDynamicSharedMemorySize, dn_smem);

    float *x_tf, *wgut, *wdt;
    cudaGetSymbolAddress((void**)&x_tf, g_x_tf);
    cudaGetSymbolAddress((void**)&wgut, g_wgut);
    cudaGetSymbolAddress((void**)&wdt,  g_wdt);

    cudaMemsetAsync(out, 0, (size_t)out_size * sizeof(float));
    zero_counts_kernel<<<1, 32>>>();

    const int xn4 = NTOK * DIM / 4;
    round_tf32_kernel<<<(xn4 + 255) / 256, 256>>>(x, x_tf, xn4);
    // wgu [e][512][2048] -> wgut [e][2048][512]
    transpose_tf32_kernel<<<dim3(2 * FDIM / 32, DIM / 128, NEXP), 256>>>(wgu, wgut, DIM, 2 * FDIM);
    // wd [e][1024][512] -> wdt [e][512][1024]
    transpose_tf32_kernel<<<dim3(DIM / 32, FDIM / 128, NEXP), 256>>>(wd, wdt, FDIM, DIM);

    router_kernel<<<NTOK / 8, 256>>>(x, rw, rb);
    gateup_kernel<<<dim3(FDIM / BN, NTOK / BM, NEXP), 256, gu_smem>>>(x_tf, wgut);
    down_kernel<<<dim3(DIM / BN, NTOK / BM, NEXP), 256, dn_smem>>>(wdt, out);
}

// round 11
// speedup vs baseline: 2.1031x; 2.1031x over previous
#include <cuda_runtime.h>
#include <math.h>
#include <stdint.h>

// Problem shape (fixed)
#define NTOK 8192      // B*T
#define DIM  512       // D
#define FDIM 1024      // F
#define NEXP 8         // E

// ---------------- scratch ----------------
__device__ int   g_expert_count[NEXP];
__device__ int   g_expert_pair[NEXP * NTOK];
__device__ float g_pair_w[NTOK * 2];
__device__ float g_hbuf[(size_t)NTOK * 2 * FDIM];        // SwiGLU act (tf32-rounded)
__device__ float g_x_tf[(size_t)NTOK * DIM];             // tf32-rounded x
__device__ float g_wgut[(size_t)NEXP * 2 * FDIM * DIM];  // [e][n(2F)][k(D)] transposed+rounded
__device__ float g_wdt[(size_t)NEXP * DIM * FDIM];       // [e][n(D)][k(F)] transposed+rounded

// ---------------- PTX helpers ----------------
__device__ __forceinline__ uint32_t smem_u32(const void* p) {
    return (uint32_t)__cvta_generic_to_shared(p);
}
__device__ __forceinline__ void cpa16(uint32_t dst, const void* src, int sz) {
    asm volatile("cp.async.cg.shared.global [%0], [%1], 16, %2;\n"
                 :: "r"(dst), "l"(src), "r"(sz));
}
__device__ __forceinline__ void cp_commit() { asm volatile("cp.async.commit_group;\n"); }
template <int N>
__device__ __forceinline__ void cp_wait() { asm volatile("cp.async.wait_group %0;\n" :: "n"(N)); }
__device__ __forceinline__ uint32_t f2tf(float f) {
    uint32_t u; asm("cvt.rna.tf32.f32 %0, %1;" : "=r"(u) : "f"(f)); return u;
}
__device__ __forceinline__ void ldsm4(uint32_t* r, uint32_t addr) {
    asm volatile("ldmatrix.sync.aligned.m8n8.x4.shared.b16 {%0,%1,%2,%3}, [%4];"
                 : "=r"(r[0]), "=r"(r[1]), "=r"(r[2]), "=r"(r[3]) : "r"(addr));
}
__device__ __forceinline__ void mma8(float* d, const uint32_t* a, const uint32_t* b) {
    asm volatile("mma.sync.aligned.m16n8k8.row.col.f32.tf32.tf32.f32 "
                 "{%0,%1,%2,%3}, {%4,%5,%6,%7}, {%8,%9}, {%0,%1,%2,%3};\n"
                 : "+f"(d[0]), "+f"(d[1]), "+f"(d[2]), "+f"(d[3])
                 : "r"(a[0]), "r"(a[1]), "r"(a[2]), "r"(a[3]),
                   "r"(b[0]), "r"(b[1]));
}

// ---------------- kernel: pre-round x -> tf32(rna) ----------------
__global__ void __launch_bounds__(256) round_tf32_kernel(const float* __restrict__ src,
                                                         float* __restrict__ dst, int n4) {
    int i = blockIdx.x * 256 + threadIdx.x;
    if (i >= n4) return;
    float4 v = reinterpret_cast<const float4*>(src)[i];
    float4 o;
    o.x = __uint_as_float(f2tf(v.x));
    o.y = __uint_as_float(f2tf(v.y));
    o.z = __uint_as_float(f2tf(v.z));
    o.w = __uint_as_float(f2tf(v.w));
    reinterpret_cast<float4*>(dst)[i] = o;
}

// ---------------- kernel: fused transpose + tf32(rna) round ----------------
__global__ void __launch_bounds__(256) transpose_tf32_kernel(const float* __restrict__ in,
                                                             float* __restrict__ out,
                                                             int R, int C) {
    __shared__ float t[4][32][33];
    size_t zoff = (size_t)blockIdx.z * (size_t)R * C;
    in += zoff; out += zoff;
    int r0 = blockIdx.y * 128, c0 = blockIdx.x * 32;
    int tid = threadIdx.x;
    int row32 = tid >> 3, c4 = tid & 7;
    float4 v[4];
#pragma unroll
    for (int i = 0; i < 4; i++)
        v[i] = *reinterpret_cast<const float4*>(
            in + (size_t)(r0 + i * 32 + row32) * C + c0 + c4 * 4);
#pragma unroll
    for (int i = 0; i < 4; i++) {
        t[i][c4 * 4 + 0][row32] = v[i].x;
        t[i][c4 * 4 + 1][row32] = v[i].y;
        t[i][c4 * 4 + 2][row32] = v[i].z;
        t[i][c4 * 4 + 3][row32] = v[i].w;
    }
    __syncthreads();
    int oc = tid >> 3, o4 = tid & 7;
#pragma unroll
    for (int i = 0; i < 4; i++) {
        float4 o;
        o.x = __uint_as_float(f2tf(t[i][oc][o4 * 4 + 0]));
        o.y = __uint_as_float(f2tf(t[i][oc][o4 * 4 + 1]));
        o.z = __uint_as_float(f2tf(t[i][oc][o4 * 4 + 2]));
        o.w = __uint_as_float(f2tf(t[i][oc][o4 * 4 + 3]));
        *reinterpret_cast<float4*>(out + (size_t)(c0 + oc) * R + r0 + i * 32 + o4 * 4) = o;
    }
}

// ---------------- kernel 0: zero counts ----------------
__global__ void zero_counts_kernel() {
    if (threadIdx.x < NEXP) g_expert_count[threadIdx.x] = 0;
}

// ---------------- kernel 1: router + dispatch ----------------
__global__ void router_kernel(const float* __restrict__ x,
                              const float* __restrict__ rw,
                              const float* __restrict__ rb) {
    __shared__ float sw[NEXP * DIM];
    int tid = threadIdx.x;
    for (int i = tid; i < NEXP * DIM; i += 256) sw[i] = rw[i];
    __syncthreads();

    int warp = tid >> 5, lane = tid & 31;
    int token = blockIdx.x * 8 + warp;
    if (token >= NTOK) return;

    const float* xr = x + (size_t)token * DIM;
    float acc[NEXP];
#pragma unroll
    for (int e = 0; e < NEXP; e++) acc[e] = 0.f;
    for (int i = lane; i < DIM; i += 32) {
        float xv = xr[i];
#pragma unroll
        for (int e = 0; e < NEXP; e++) acc[e] += xv * sw[e * DIM + i];
    }
#pragma unroll
    for (int e = 0; e < NEXP; e++) {
#pragma unroll
        for (int o = 16; o > 0; o >>= 1)
            acc[e] += __shfl_xor_sync(0xffffffffu, acc[e], o);
    }
    if (lane == 0) {
        float l[NEXP];
#pragma unroll
        for (int e = 0; e < NEXP; e++) l[e] = acc[e] + rb[e];
        int e1 = 0; float b1 = l[0];
#pragma unroll
        for (int e = 1; e < NEXP; e++) if (l[e] > b1) { b1 = l[e]; e1 = e; }
        int e2 = -1; float b2 = -INFINITY;
#pragma unroll
        for (int e = 0; e < NEXP; e++)
            if (e != e1 && l[e] > b2) { b2 = l[e]; e2 = e; }
        float t  = expf(b2 - b1);
        float w1 = 1.f / (1.f + t);
        float w2 = t   / (1.f + t);
        int pos1 = atomicAdd(&g_expert_count[e1], 1);
        g_expert_pair[e1 * NTOK + pos1] = token * 2;
        g_pair_w[token * 2] = w1;
        int pos2 = atomicAdd(&g_expert_count[e2], 1);
        g_expert_pair[e2 * NTOK + pos2] = token * 2 + 1;
        g_pair_w[token * 2 + 1] = w2;
    }
}

// ---------------- tensor-GEMM config ----------------
#define BM 128
#define BN 64
#define BK 32
#define BKP 36
#define ASZ (BM * BKP)
#define BSZ (BN * BKP)
// 8 warps = 4 m-groups x 2 n-groups; warp tile 32x32

// ---------------- kernel 2: gate_up GEMM + SwiGLU ----------------
__global__ void __launch_bounds__(256, 2)
gateup_kernel(const float* __restrict__ x, const float* __restrict__ wgut) {
    int e = blockIdx.z;
    int count = g_expert_count[e];
    int m0 = blockIdx.y * BM;
    if (m0 >= count) return;
    int n0 = blockIdx.x * BN;
    int tid = threadIdx.x;

    extern __shared__ float dynsmem[];
    __shared__ int s_pr[BM];
    if (tid < BM) {
        int m = m0 + tid;
        s_pr[tid] = (m < count) ? g_expert_pair[e * NTOK + m] : -1;
    }
    __syncthreads();

    const float* wge = wgut + (size_t)e * (2 * FDIM) * DIM;
    float* stage0 = dynsmem;
    float* stage1 = dynsmem + (ASZ + 2 * BSZ);

    int am[4], ac[4], asz[4];
    const float* asrc[4];
#pragma unroll
    for (int j = 0; j < 4; j++) {
        int idx = tid + 256 * j;
        am[j] = idx >> 3; ac[j] = (idx & 7) * 4;
        int pr = s_pr[am[j]];
        asz[j]  = (pr >= 0) ? 16 : 0;
        asrc[j] = (pr >= 0) ? (x + (size_t)(pr >> 1) * DIM + ac[j]) : x;
    }
    int brow[2], bch[2];
#pragma unroll
    for (int j = 0; j < 2; j++) {
        int idx = tid + 256 * j;
        brow[j] = idx >> 3; bch[j] = (idx & 7) * 4;
    }

    auto load_tile = [&](int kt, float* st) {
        float* As = st; float* Bg = st + ASZ; float* Bu = Bg + BSZ;
        int k0 = kt * BK;
#pragma unroll
        for (int j = 0; j < 4; j++)
            cpa16(smem_u32(As + am[j] * BKP + ac[j]), asrc[j] + k0, asz[j]);
#pragma unroll
        for (int j = 0; j < 2; j++) {
            cpa16(smem_u32(Bg + brow[j] * BKP + bch[j]),
                  wge + (size_t)(n0 + brow[j]) * DIM + k0 + bch[j], 16);
            cpa16(smem_u32(Bu + brow[j] * BKP + bch[j]),
                  wge + (size_t)(FDIM + n0 + brow[j]) * DIM + k0 + bch[j], 16);
        }
    };

    int lane = tid & 31, warp = tid >> 5;
    int wm = (warp & 3) * 32, wn = (warp >> 2) * 32;
    int r = lane >> 2, c = lane & 3;
    int lrow = lane & 15, lcol = (lane >> 4) * 4;
    int nbr  = ((lane >> 4) * 8) + (lane & 7);
    int kh   = ((lane >> 3) & 1) * 4;

    float accg[2][4][4] = {{{0.f}}};
    float accu[2][4][4] = {{{0.f}}};

    load_tile(0, stage0);
    cp_commit();
    const int KT = DIM / BK;   // 16
    for (int kt = 0; kt < KT; kt++) {
        if (kt + 1 < KT) load_tile(kt + 1, ((kt + 1) & 1) ? stage1 : stage0);
        cp_commit();
        cp_wait<1>();
        __syncthreads();
        const float* As = (kt & 1) ? stage1 : stage0;
        uint32_t abase = smem_u32(As + (wm + lrow) * BKP + lcol);
        uint32_t gbase = smem_u32(As + ASZ + (wn + nbr) * BKP + kh);
        uint32_t ubase = gbase + BSZ * 4;
#pragma unroll
        for (int k8 = 0; k8 < BK / 8; k8++) {
            uint32_t a[2][4];
#pragma unroll
            for (int i = 0; i < 2; i++)
                ldsm4(a[i], abase + i * (16 * BKP * 4) + k8 * 32);
            // one 4-reg B fragment live at a time (register budget <=128)
#pragma unroll
            for (int jj = 0; jj < 2; jj++) {
                uint32_t bf[4];
                ldsm4(bf, gbase + jj * (16 * BKP * 4) + k8 * 32);
#pragma unroll
                for (int i = 0; i < 2; i++) {
                    mma8(accg[i][jj * 2 + 0], a[i], &bf[0]);
                    mma8(accg[i][jj * 2 + 1], a[i], &bf[2]);
                }
                ldsm4(bf, ubase + jj * (16 * BKP * 4) + k8 * 32);
#pragma unroll
                for (int i = 0; i < 2; i++) {
                    mma8(accu[i][jj * 2 + 0], a[i], &bf[0]);
                    mma8(accu[i][jj * 2 + 1], a[i], &bf[2]);
                }
            }
        }
        __syncthreads();
    }

    // epilogue: silu(g)*u -> hbuf (tf32-rounded so down needs no A cvt)
#pragma unroll
    for (int i = 0; i < 2; i++) {
#pragma unroll
        for (int rr = 0; rr < 2; rr++) {
            int mrow = wm + i * 16 + r + rr * 8;
            int pr = s_pr[mrow];
            if (pr < 0) continue;
            float* hp = g_hbuf + (size_t)pr * FDIM + n0 + wn;
#pragma unroll
            for (int j = 0; j < 4; j++) {
                float g0 = accg[i][j][rr * 2 + 0], g1 = accg[i][j][rr * 2 + 1];
                float u0 = accu[i][j][rr * 2 + 0], u1 = accu[i][j][rr * 2 + 1];
                float h0 = g0 / (1.f + expf(-g0)) * u0;
                float h1 = g1 / (1.f + expf(-g1)) * u1;
                float2 hv = make_float2(__uint_as_float(f2tf(h0)),
                                        __uint_as_float(f2tf(h1)));
                *reinterpret_cast<float2*>(hp + j * 8 + 2 * c) = hv;
            }
        }
    }
}

// ---------------- kernel 3: down GEMM + weighted combine ----------------
__global__ void __launch_bounds__(256, 2)
down_kernel(const float* __restrict__ wdt, float* __restrict__ out) {
    int e = blockIdx.z;
    int count = g_expert_count[e];
    int m0 = blockIdx.y * BM;
    if (m0 >= count) return;
    int n0 = blockIdx.x * BN;
    int tid = threadIdx.x;

    extern __shared__ float dynsmem[];
    __shared__ int   s_pr[BM];
    __shared__ float s_w[BM];
    if (tid < BM) {
        int m = m0 + tid;
        int pr = (m < count) ? g_expert_pair[e * NTOK + m] : -1;
        s_pr[tid] = pr;
        s_w[tid]  = (pr >= 0) ? g_pair_w[pr] : 0.f;
    }
    __syncthreads();

    const float* wde = wdt + (size_t)e * DIM * FDIM;
    float* stage0 = dynsmem;
    float* stage1 = dynsmem + (ASZ + BSZ);

    int am[4], ac[4], asz[4];
    const float* asrc[4];
#pragma unroll
    for (int j = 0; j < 4; j++) {
        int idx = tid + 256 * j;
        am[j] = idx >> 3; ac[j] = (idx & 7) * 4;
        int pr = s_pr[am[j]];
        asz[j]  = (pr >= 0) ? 16 : 0;
        asrc[j] = (pr >= 0) ? (g_hbuf + (size_t)pr * FDIM + ac[j]) : g_hbuf;
    }
    int brow[2], bch[2];
#pragma unroll
    for (int j = 0; j < 2; j++) {
        int idx = tid + 256 * j;
        brow[j] = idx >> 3; bch[j] = (idx & 7) * 4;
    }

    auto load_tile = [&](int kt, float* st) {
        float* As = st; float* Bs = st + ASZ;
        int k0 = kt * BK;
#pragma unroll
        for (int j = 0; j < 4; j++)
            cpa16(smem_u32(As + am[j] * BKP + ac[j]), asrc[j] + k0, asz[j]);
#pragma unroll
        for (int j = 0; j < 2; j++)
            cpa16(smem_u32(Bs + brow[j] * BKP + bch[j]),
                  wde + (size_t)(n0 + brow[j]) * FDIM + k0 + bch[j], 16);
    };

    int lane = tid & 31, warp = tid >> 5;
    int wm = (warp & 3) * 32, wn = (warp >> 2) * 32;
    int r = lane >> 2, c = lane & 3;
    int lrow = lane & 15, lcol = (lane >> 4) * 4;
    int nbr  = ((lane >> 4) * 8) + (lane & 7);
    int kh   = ((lane >> 3) & 1) * 4;

    float acc[2][4][4] = {{{0.f}}};

    load_tile(0, stage0);
    cp_commit();
    const int KT = FDIM / BK;  // 32
    for (int kt = 0; kt < KT; kt++) {
        if (kt + 1 < KT) load_tile(kt + 1, ((kt + 1) & 1) ? stage1 : stage0);
        cp_commit();
        cp_wait<1>();
        __syncthreads();
        const float* As = (kt & 1) ? stage1 : stage0;
        uint32_t abase = smem_u32(As + (wm + lrow) * BKP + lcol);
        uint32_t bbase = smem_u32(As + ASZ + (wn + nbr) * BKP + kh);
#pragma unroll
        for (int k8 = 0; k8 < BK / 8; k8++) {
            uint32_t a[2][4];
#pragma unroll
            for (int i = 0; i < 2; i++)
                ldsm4(a[i], abase + i * (16 * BKP * 4) + k8 * 32);
#pragma unroll
            for (int jj = 0; jj < 2; jj++) {
                uint32_t bf[4];
                ldsm4(bf, bbase + jj * (16 * BKP * 4) + k8 * 32);
#pragma unroll
                for (int i = 0; i < 2; i++) {
                    mma8(acc[i][jj * 2 + 0], a[i], &bf[0]);
                    mma8(acc[i][jj * 2 + 1], a[i], &bf[2]);
                }
            }
        }
        __syncthreads();
    }

    // epilogue: out += w * acc (2 commutative atomics per element)
#pragma unroll
    for (int i = 0; i < 2; i++) {
#pragma unroll
        for (int rr = 0; rr < 2; rr++) {
            int mrow = wm + i * 16 + r + rr * 8;
            int pr = s_pr[mrow];
            if (pr < 0) continue;
            int token = pr >> 1;
            float w = s_w[mrow];
            float* op = out + (size_t)token * DIM + n0 + wn;
#pragma unroll
            for (int j = 0; j < 4; j++) {
                atomicAdd(op + j * 8 + 2 * c,     w * acc[i][j][rr * 2 + 0]);
                atomicAdd(op + j * 8 + 2 * c + 1, w * acc[i][j][rr * 2 + 1]);
            }
        }
    }
}

// ---------------- launch ----------------
extern "C" void kernel_launch(void* const* d_in, const int* in_sizes, int n_in,
                              void* d_out, int out_size) {
    const float* x   = (const float*)d_in[0];
    const float* rw  = (const float*)d_in[1];
    const float* rb  = (const float*)d_in[2];
    const float* wgu = (const float*)d_in[3];
    const float* wd  = (const float*)d_in[4];
    float* out = (float*)d_out;

    const int gu_smem = 2 * (ASZ + 2 * BSZ) * 4;   // 73728 B
    const int dn_smem = 2 * (ASZ + BSZ) * 4;       // 55296 B
    cudaFuncSetAttribute(gateup_kernel, cudaFuncAttributeMaxDynamicSharedMemorySize, gu_smem);
    cudaFuncSetAttribute(down_kernel,   cudaFuncAttributeMaxDynamicSharedMemorySize, dn_smem);

    float *x_tf, *wgut, *wdt;
    cudaGetSymbolAddress((void**)&x_tf, g_x_tf);
    cudaGetSymbolAddress((void**)&wgut, g_wgut);
    cudaGetSymbolAddress((void**)&wdt,  g_wdt);

    cudaMemsetAsync(out, 0, (size_t)out_size * sizeof(float));
    zero_counts_kernel<<<1, 32>>>();

    const int xn4 = NTOK * DIM / 4;
    round_tf32_kernel<<<(xn4 + 255) / 256, 256>>>(x, x_tf, xn4);
    transpose_tf32_kernel<<<dim3(2 * FDIM / 32, DIM / 128, NEXP), 256>>>(wgu, wgut, DIM, 2 * FDIM);
    transpose_tf32_kernel<<<dim3(DIM / 32, FDIM / 128, NEXP), 256>>>(wd, wdt, FDIM, DIM);

    router_kernel<<<NTOK / 8, 256>>>(x, rw, rb);
    gateup_kernel<<<dim3(FDIM / BN, NTOK / BM, NEXP), 256, gu_smem>>>(x_tf, wgut);
    down_kernel<<<dim3(DIM / BN, NTOK / BM, NEXP), 256, dn_smem>>>(wdt, out);
}

// round 14
// speedup vs baseline: 2.1052x; 1.0010x over previous
#include <cuda_runtime.h>
#include <math.h>
#include <stdint.h>

// Problem shape (fixed)
#define NTOK 8192      // B*T
#define DIM  512       // D
#define FDIM 1024      // F
#define NEXP 8         // E

// ---------------- scratch ----------------
__device__ int   g_expert_count[NEXP];
__device__ int   g_expert_pair[NEXP * NTOK];
__device__ float g_pair_w[NTOK * 2];
__device__ float g_hbuf[(size_t)NTOK * 2 * FDIM];        // SwiGLU act (tf32-rounded)
__device__ float g_x_tf[(size_t)NTOK * DIM];             // tf32-rounded x
__device__ float g_wgut[(size_t)NEXP * 2 * FDIM * DIM];  // [e][n(2F)][k(D)] transposed+rounded
__device__ float g_wdt[(size_t)NEXP * DIM * FDIM];       // [e][n(D)][k(F)] transposed+rounded

// ---------------- PTX helpers ----------------
__device__ __forceinline__ uint32_t smem_u32(const void* p) {
    return (uint32_t)__cvta_generic_to_shared(p);
}
__device__ __forceinline__ void cpa16(uint32_t dst, const void* src, int sz) {
    asm volatile("cp.async.cg.shared.global [%0], [%1], 16, %2;\n"
                 :: "r"(dst), "l"(src), "r"(sz));
}
__device__ __forceinline__ void cp_commit() { asm volatile("cp.async.commit_group;\n"); }
template <int N>
__device__ __forceinline__ void cp_wait() { asm volatile("cp.async.wait_group %0;\n" :: "n"(N)); }
__device__ __forceinline__ uint32_t f2tf(float f) {
    uint32_t u; asm("cvt.rna.tf32.f32 %0, %1;" : "=r"(u) : "f"(f)); return u;
}
__device__ __forceinline__ void ldsm4(uint32_t* r, uint32_t addr) {
    asm volatile("ldmatrix.sync.aligned.m8n8.x4.shared.b16 {%0,%1,%2,%3}, [%4];"
                 : "=r"(r[0]), "=r"(r[1]), "=r"(r[2]), "=r"(r[3]) : "r"(addr));
}
__device__ __forceinline__ void mma8(float* d, const uint32_t* a, const uint32_t* b) {
    asm volatile("mma.sync.aligned.m16n8k8.row.col.f32.tf32.tf32.f32 "
                 "{%0,%1,%2,%3}, {%4,%5,%6,%7}, {%8,%9}, {%0,%1,%2,%3};\n"
                 : "+f"(d[0]), "+f"(d[1]), "+f"(d[2]), "+f"(d[3])
                 : "r"(a[0]), "r"(a[1]), "r"(a[2]), "r"(a[3]),
                   "r"(b[0]), "r"(b[1]));
}

// ---------------- kernel: pre-round x -> tf32(rna) ----------------
__global__ void __launch_bounds__(256) round_tf32_kernel(const float* __restrict__ src,
                                                         float* __restrict__ dst, int n4) {
    int i = blockIdx.x * 256 + threadIdx.x;
    if (i >= n4) return;
    float4 v = reinterpret_cast<const float4*>(src)[i];
    float4 o;
    o.x = __uint_as_float(f2tf(v.x));
    o.y = __uint_as_float(f2tf(v.y));
    o.z = __uint_as_float(f2tf(v.z));
    o.w = __uint_as_float(f2tf(v.w));
    reinterpret_cast<float4*>(dst)[i] = o;
}

// ---------------- kernel: fused transpose + tf32(rna) round ----------------
__global__ void __launch_bounds__(256) transpose_tf32_kernel(const float* __restrict__ in,
                                                             float* __restrict__ out,
                                                             int R, int C) {
    __shared__ float t[4][32][33];
    size_t zoff = (size_t)blockIdx.z * (size_t)R * C;
    in += zoff; out += zoff;
    int r0 = blockIdx.y * 128, c0 = blockIdx.x * 32;
    int tid = threadIdx.x;
    int row32 = tid >> 3, c4 = tid & 7;
    float4 v[4];
#pragma unroll
    for (int i = 0; i < 4; i++)
        v[i] = *reinterpret_cast<const float4*>(
            in + (size_t)(r0 + i * 32 + row32) * C + c0 + c4 * 4);
#pragma unroll
    for (int i = 0; i < 4; i++) {
        t[i][c4 * 4 + 0][row32] = v[i].x;
        t[i][c4 * 4 + 1][row32] = v[i].y;
        t[i][c4 * 4 + 2][row32] = v[i].z;
        t[i][c4 * 4 + 3][row32] = v[i].w;
    }
    __syncthreads();
    int oc = tid >> 3, o4 = tid & 7;
#pragma unroll
    for (int i = 0; i < 4; i++) {
        float4 o;
        o.x = __uint_as_float(f2tf(t[i][oc][o4 * 4 + 0]));
        o.y = __uint_as_float(f2tf(t[i][oc][o4 * 4 + 1]));
        o.z = __uint_as_float(f2tf(t[i][oc][o4 * 4 + 2]));
        o.w = __uint_as_float(f2tf(t[i][oc][o4 * 4 + 3]));
        *reinterpret_cast<float4*>(out + (size_t)(c0 + oc) * R + r0 + i * 32 + o4 * 4) = o;
    }
}

// ---------------- kernel 0: zero counts ----------------
__global__ void zero_counts_kernel() {
    if (threadIdx.x < NEXP) g_expert_count[threadIdx.x] = 0;
}

// ---------------- kernel 1: router + dispatch ----------------
__global__ void router_kernel(const float* __restrict__ x,
                              const float* __restrict__ rw,
                              const float* __restrict__ rb) {
    __shared__ float sw[NEXP * DIM];
    int tid = threadIdx.x;
    for (int i = tid; i < NEXP * DIM; i += 256) sw[i] = rw[i];
    __syncthreads();

    int warp = tid >> 5, lane = tid & 31;
    int token = blockIdx.x * 8 + warp;
    if (token >= NTOK) return;

    const float* xr = x + (size_t)token * DIM;
    float acc[NEXP];
#pragma unroll
    for (int e = 0; e < NEXP; e++) acc[e] = 0.f;
    for (int i = lane; i < DIM; i += 32) {
        float xv = xr[i];
#pragma unroll
        for (int e = 0; e < NEXP; e++) acc[e] += xv * sw[e * DIM + i];
    }
#pragma unroll
    for (int e = 0; e < NEXP; e++) {
#pragma unroll
        for (int o = 16; o > 0; o >>= 1)
            acc[e] += __shfl_xor_sync(0xffffffffu, acc[e], o);
    }
    if (lane == 0) {
        float l[NEXP];
#pragma unroll
        for (int e = 0; e < NEXP; e++) l[e] = acc[e] + rb[e];
        int e1 = 0; float b1 = l[0];
#pragma unroll
        for (int e = 1; e < NEXP; e++) if (l[e] > b1) { b1 = l[e]; e1 = e; }
        int e2 = -1; float b2 = -INFINITY;
#pragma unroll
        for (int e = 0; e < NEXP; e++)
            if (e != e1 && l[e] > b2) { b2 = l[e]; e2 = e; }
        float t  = expf(b2 - b1);
        float w1 = 1.f / (1.f + t);
        float w2 = t   / (1.f + t);
        int pos1 = atomicAdd(&g_expert_count[e1], 1);
        g_expert_pair[e1 * NTOK + pos1] = token * 2;
        g_pair_w[token * 2] = w1;
        int pos2 = atomicAdd(&g_expert_count[e2], 1);
        g_expert_pair[e2 * NTOK + pos2] = token * 2 + 1;
        g_pair_w[token * 2 + 1] = w2;
    }
}

// ---------------- tensor-GEMM config ----------------
#define BM 128
#define BK 32
#define BKP 36
#define ASZ (BM * BKP)        // 4608 words
#define BNG 64                // gateup N per matrix
#define BSZG (BNG * BKP)      // 2304 words
#define PITCHG (ASZ + 2 * BSZG)   // 9216 words per stage
#define BND 128               // down N
#define BSZD (BND * BKP)      // 4608 words

// ---------------- kernel 2: gate_up GEMM + SwiGLU (3-stage) ----------------
// grid = (FDIM/BNG, NTOK/BM, NEXP)
__global__ void __launch_bounds__(256, 2)
gateup_kernel(const float* __restrict__ x, const float* __restrict__ wgut) {
    int e = blockIdx.z;
    int count = g_expert_count[e];
    int m0 = blockIdx.y * BM;
    if (m0 >= count) return;
    int n0 = blockIdx.x * BNG;
    int tid = threadIdx.x;

    extern __shared__ float dynsmem[];
    __shared__ int s_pr[BM];
    if (tid < BM) {
        int m = m0 + tid;
        s_pr[tid] = (m < count) ? g_expert_pair[e * NTOK + m] : -1;
    }
    __syncthreads();

    const float* wge = wgut + (size_t)e * (2 * FDIM) * DIM;

    int am[4], ac[4], asz[4];
    const float* asrc[4];
#pragma unroll
    for (int j = 0; j < 4; j++) {
        int idx = tid + 256 * j;
        am[j] = idx >> 3; ac[j] = (idx & 7) * 4;
        int pr = s_pr[am[j]];
        asz[j]  = (pr >= 0) ? 16 : 0;
        asrc[j] = (pr >= 0) ? (x + (size_t)(pr >> 1) * DIM + ac[j]) : x;
    }
    int brow[2], bch[2];
#pragma unroll
    for (int j = 0; j < 2; j++) {
        int idx = tid + 256 * j;
        brow[j] = idx >> 3; bch[j] = (idx & 7) * 4;
    }

    auto load_tile = [&](int kt) {
        float* st = dynsmem + (kt % 3) * PITCHG;
        float* As = st; float* Bg = st + ASZ; float* Bu = Bg + BSZG;
        int k0 = kt * BK;
#pragma unroll
        for (int j = 0; j < 4; j++)
            cpa16(smem_u32(As + am[j] * BKP + ac[j]), asrc[j] + k0, asz[j]);
#pragma unroll
        for (int j = 0; j < 2; j++) {
            cpa16(smem_u32(Bg + brow[j] * BKP + bch[j]),
                  wge + (size_t)(n0 + brow[j]) * DIM + k0 + bch[j], 16);
            cpa16(smem_u32(Bu + brow[j] * BKP + bch[j]),
                  wge + (size_t)(FDIM + n0 + brow[j]) * DIM + k0 + bch[j], 16);
        }
    };

    int lane = tid & 31, warp = tid >> 5;
    int wm = (warp & 3) * 32, wn = (warp >> 2) * 32;
    int r = lane >> 2, c = lane & 3;
    int lrow = lane & 15, lcol = (lane >> 4) * 4;
    int nbr  = ((lane >> 4) * 8) + (lane & 7);
    int kh   = ((lane >> 3) & 1) * 4;

    float accg[2][4][4] = {{{0.f}}};
    float accu[2][4][4] = {{{0.f}}};

    load_tile(0); cp_commit();
    load_tile(1); cp_commit();
    const int KT = DIM / BK;   // 16
    for (int kt = 0; kt < KT; kt++) {
        cp_wait<1>();           // tile kt landed
        __syncthreads();        // all warps done with tile kt-1 (stage (kt+2)%3)
        if (kt + 2 < KT) load_tile(kt + 2);
        cp_commit();
        const float* As = dynsmem + (kt % 3) * PITCHG;
        uint32_t abase = smem_u32(As + (wm + lrow) * BKP + lcol);
        uint32_t gbase = smem_u32(As + ASZ + (wn + nbr) * BKP + kh);
        uint32_t ubase = gbase + BSZG * 4;
#pragma unroll
        for (int k8 = 0; k8 < BK / 8; k8++) {
            uint32_t a[2][4];
#pragma unroll
            for (int i = 0; i < 2; i++)
                ldsm4(a[i], abase + i * (16 * BKP * 4) + k8 * 32);
#pragma unroll
            for (int jj = 0; jj < 2; jj++) {
                uint32_t bf[4];
                ldsm4(bf, gbase + jj * (16 * BKP * 4) + k8 * 32);
#pragma unroll
                for (int i = 0; i < 2; i++) {
                    mma8(accg[i][jj * 2 + 0], a[i], &bf[0]);
                    mma8(accg[i][jj * 2 + 1], a[i], &bf[2]);
                }
                ldsm4(bf, ubase + jj * (16 * BKP * 4) + k8 * 32);
#pragma unroll
                for (int i = 0; i < 2; i++) {
                    mma8(accu[i][jj * 2 + 0], a[i], &bf[0]);
                    mma8(accu[i][jj * 2 + 1], a[i], &bf[2]);
                }
            }
        }
    }

    // epilogue: silu(g)*u -> hbuf (tf32-rounded so down needs no A cvt)
#pragma unroll
    for (int i = 0; i < 2; i++) {
#pragma unroll
        for (int rr = 0; rr < 2; rr++) {
            int mrow = wm + i * 16 + r + rr * 8;
            int pr = s_pr[mrow];
            if (pr < 0) continue;
            float* hp = g_hbuf + (size_t)pr * FDIM + n0 + wn;
#pragma unroll
            for (int j = 0; j < 4; j++) {
                float g0 = accg[i][j][rr * 2 + 0], g1 = accg[i][j][rr * 2 + 1];
                float u0 = accu[i][j][rr * 2 + 0], u1 = accu[i][j][rr * 2 + 1];
                float h0 = g0 / (1.f + expf(-g0)) * u0;
                float h1 = g1 / (1.f + expf(-g1)) * u1;
                float2 hv = make_float2(__uint_as_float(f2tf(h0)),
                                        __uint_as_float(f2tf(h1)));
                *reinterpret_cast<float2*>(hp + j * 8 + 2 * c) = hv;
            }
        }
    }
}

// ---------------- kernel 3: down GEMM + weighted combine (BN=128) ----------------
// grid = (DIM/BND, NTOK/BM, NEXP); warp tile 32x64
__global__ void __launch_bounds__(256, 2)
down_kernel(const float* __restrict__ wdt, float* __restrict__ out) {
    int e = blockIdx.z;
    int count = g_expert_count[e];
    int m0 = blockIdx.y * BM;
    if (m0 >= count) return;
    int n0 = blockIdx.x * BND;
    int tid = threadIdx.x;

    extern __shared__ float dynsmem[];
    __shared__ int   s_pr[BM];
    __shared__ float s_w[BM];
    if (tid < BM) {
        int m = m0 + tid;
        int pr = (m < count) ? g_expert_pair[e * NTOK + m] : -1;
        s_pr[tid] = pr;
        s_w[tid]  = (pr >= 0) ? g_pair_w[pr] : 0.f;
    }
    __syncthreads();

    const float* wde = wdt + (size_t)e * DIM * FDIM;
    float* stage0 = dynsmem;
    float* stage1 = dynsmem + (ASZ + BSZD);

    int am[4], ac[4], asz[4];
    const float* asrc[4];
#pragma unroll
    for (int j = 0; j < 4; j++) {
        int idx = tid + 256 * j;
        am[j] = idx >> 3; ac[j] = (idx & 7) * 4;
        int pr = s_pr[am[j]];
        asz[j]  = (pr >= 0) ? 16 : 0;
        asrc[j] = (pr >= 0) ? (g_hbuf + (size_t)pr * FDIM + ac[j]) : g_hbuf;
    }
    int brow[4], bch[4];
#pragma unroll
    for (int j = 0; j < 4; j++) {
        int idx = tid + 256 * j;
        brow[j] = idx >> 3; bch[j] = (idx & 7) * 4;
    }

    auto load_tile = [&](int kt, float* st) {
        float* As = st; float* Bs = st + ASZ;
        int k0 = kt * BK;
#pragma unroll
        for (int j = 0; j < 4; j++)
            cpa16(smem_u32(As + am[j] * BKP + ac[j]), asrc[j] + k0, asz[j]);
#pragma unroll
        for (int j = 0; j < 4; j++)
            cpa16(smem_u32(Bs + brow[j] * BKP + bch[j]),
                  wde + (size_t)(n0 + brow[j]) * FDIM + k0 + bch[j], 16);
    };

    int lane = tid & 31, warp = tid >> 5;
    int wm = (warp & 3) * 32, wn = (warp >> 2) * 64;
    int r = lane >> 2, c = lane & 3;
    int lrow = lane & 15, lcol = (lane >> 4) * 4;
    int nbr  = ((lane >> 4) * 8) + (lane & 7);
    int kh   = ((lane >> 3) & 1) * 4;

    float acc[2][8][4] = {{{0.f}}};

    load_tile(0, stage0);
    cp_commit();
    const int KT = FDIM / BK;  // 32
    for (int kt = 0; kt < KT; kt++) {
        if (kt + 1 < KT) load_tile(kt + 1, ((kt + 1) & 1) ? stage1 : stage0);
        cp_commit();
        cp_wait<1>();
        __syncthreads();
        const float* As = (kt & 1) ? stage1 : stage0;
        uint32_t abase = smem_u32(As + (wm + lrow) * BKP + lcol);
        uint32_t bbase = smem_u32(As + ASZ + (wn + nbr) * BKP + kh);
#pragma unroll
        for (int k8 = 0; k8 < BK / 8; k8++) {
            uint32_t a[2][4];
#pragma unroll
            for (int i = 0; i < 2; i++)
                ldsm4(a[i], abase + i * (16 * BKP * 4) + k8 * 32);
#pragma unroll
            for (int jj = 0; jj < 4; jj++) {
                uint32_t bf[4];
                ldsm4(bf, bbase + jj * (16 * BKP * 4) + k8 * 32);
#pragma unroll
                for (int i = 0; i < 2; i++) {
                    mma8(acc[i][jj * 2 + 0], a[i], &bf[0]);
                    mma8(acc[i][jj * 2 + 1], a[i], &bf[2]);
                }
            }
        }
        __syncthreads();
    }

    // epilogue: out += w * acc (2 commutative atomics per element)
#pragma unroll
    for (int i = 0; i < 2; i++) {
#pragma unroll
        for (int rr = 0; rr < 2; rr++) {
            int mrow = wm + i * 16 + r + rr * 8;
            int pr = s_pr[mrow];
            if (pr < 0) continue;
            int token = pr >> 1;
            float w = s_w[mrow];
            float* op = out + (size_t)token * DIM + n0 + wn;
#pragma unroll
            for (int j = 0; j < 8; j++) {
                atomicAdd(op + j * 8 + 2 * c,     w * acc[i][j][rr * 2 + 0]);
                atomicAdd(op + j * 8 + 2 * c + 1, w * acc[i][j][rr * 2 + 1]);
            }
        }
    }
}

// ---------------- launch ----------------
extern "C" void kernel_launch(void* const* d_in, const int* in_sizes, int n_in,
                              void* d_out, int out_size) {
    const float* x   = (const float*)d_in[0];
    const float* rw  = (const float*)d_in[1];
    const float* rb  = (const float*)d_in[2];
    const float* wgu = (const float*)d_in[3];
    const float* wd  = (const float*)d_in[4];
    float* out = (float*)d_out;

    const int gu_smem = 3 * PITCHG * 4;            // 110592 B (3-stage)
    const int dn_smem = 2 * (ASZ + BSZD) * 4;      // 73728 B (2-stage)
    cudaFuncSetAttribute(gateup_kernel, cudaFuncAttributeMaxDynamicSharedMemorySize, gu_smem);
    cudaFuncSetAttribute(down_kernel,   cudaFuncAttributeMaxDynamicSharedMemorySize, dn_smem);

    float *x_tf, *wgut, *wdt;
    cudaGetSymbolAddress((void**)&x_tf, g_x_tf);
    cudaGetSymbolAddress((void**)&wgut, g_wgut);
    cudaGetSymbolAddress((void**)&wdt,  g_wdt);

    cudaMemsetAsync(out, 0, (size_t)out_size * sizeof(float));
    zero_counts_kernel<<<1, 32>>>();

    const int xn4 = NTOK * DIM / 4;
    round_tf32_kernel<<<(xn4 + 255) / 256, 256>>>(x, x_tf, xn4);
    transpose_tf32_kernel<<<dim3(2 * FDIM / 32, DIM / 128, NEXP), 256>>>(wgu, wgut, DIM, 2 * FDIM);
    transpose_tf32_kernel<<<dim3(DIM / 32, FDIM / 128, NEXP), 256>>>(wd, wdt, FDIM, DIM);

    router_kernel<<<NTOK / 8, 256>>>(x, rw, rb);
    gateup_kernel<<<dim3(FDIM / BNG, NTOK / BM, NEXP), 256, gu_smem>>>(x_tf, wgut);
    down_kernel<<<dim3(DIM / BND, NTOK / BM, NEXP), 256, dn_smem>>>(wdt, out);
}